// round 14
// baseline (speedup 1.0000x reference)
#include <cuda_runtime.h>
#include <cuda_fp16.h>
#include <cstdint>
#include <math.h>

#define EPS_   1e-5f
#define SCALE_ 0.088388347648318447f   // 1/sqrt(128)

// ---------------- static scratch ----------------
__device__ __half g_WT [3072 * 256];    // [c][k]  (QKV cat), fp16
__device__ __half g_WoT[256 * 1024];    // [c][k]  Wout^T, fp16
__device__ __half g_Ch [65536UL * 3072];// [pos][c] raw qkv, fp16
__device__ __half g_A2 [65536UL * 1024];// [pos][k] attn output, fp16

// ---------------- helpers ----------------
__device__ __forceinline__ uint32_t smem_u32(const void* p) {
    uint32_t a;
    asm("{ .reg .u64 t; cvta.to.shared.u64 t, %1; cvt.u32.u64 %0, t; }" : "=r"(a) : "l"(p));
    return a;
}

#define LDM_X4(r0, r1, r2, r3, ad) \
    asm volatile("ldmatrix.sync.aligned.m8n8.x4.shared.b16 {%0,%1,%2,%3}, [%4];" \
                 : "=r"(r0), "=r"(r1), "=r"(r2), "=r"(r3) : "r"(ad))
#define MMA16816(d, a0, a1, a2, a3, b0, b1) \
    asm volatile("mma.sync.aligned.m16n8k16.row.col.f32.f16.f16.f32 " \
                 "{%0,%1,%2,%3}, {%4,%5,%6,%7}, {%8,%9}, {%0,%1,%2,%3};" \
                 : "+f"((d)[0]), "+f"((d)[1]), "+f"((d)[2]), "+f"((d)[3]) \
                 : "r"(a0), "r"(a1), "r"(a2), "r"(a3), "r"(b0), "r"(b1))

// ============================ K0: weight prep ============================
__global__ void k0_prep(const float* __restrict__ WQ, const float* __restrict__ WK,
                        const float* __restrict__ WV, const float* __restrict__ Wout)
{
    const int i = blockIdx.x * 256 + threadIdx.x;
    if (i < 3072 * 256) {
        const int c = i >> 8, k = i & 255;
        const int t = c >> 10, r = c & 1023, n = r >> 9, cc = r & 511;
        const float* W = (t == 0) ? WQ : (t == 1) ? WK : WV;
        g_WT[i] = __float2half_rn(W[((size_t)n * 256 + k) * 512 + cc]);
    } else {
        const int j = i - 3072 * 256;
        if (j < 256 * 1024) {
            const int c = j >> 10, k = j & 1023;
            g_WoT[j] = __float2half_rn(Wout[(size_t)k * 256 + c]);
        }
    }
}

// ============================ K1: projection GEMM ============================
// C[pos][c] = X[pos][k] * WT[c][k]^T.  CTA = 128 pos x 128 c (24 chunks).
// K=256 in 2 halves of 128 so W buffer is 34816B; smem 102400 -> occ 2.
// Warp tile 64x32 (mt=4, nt=4); B ldmatrix.x4 covers two k-steps.
#define XP 264                    // X pitch (halves), 528B rows
#define WP 136                    // W / A / B pitch (halves), 272B rows
#define K1_WOFF 67584
#define K1_SMEM 102400

__global__ void __launch_bounds__(256, 2)
k1_proj(const float* __restrict__ nodal)
{
    extern __shared__ __align__(16) char sm[];
    __half* Xs = (__half*)sm;
    __half* Ws = (__half*)(sm + K1_WOFF);
    const uint32_t sb = smem_u32(sm);

    const int tid = threadIdx.x, wid = tid >> 5, lane = tid & 31;
    const int wm = wid >> 2, wn = wid & 3;   // warp: rows wm*64, cols wn*32
    const int r = tid >> 1, seg = tid & 1;
    const size_t pos0 = (size_t)blockIdx.x * 128;

    // load X tile -> fp16 smem
    {
        const float4* src = reinterpret_cast<const float4*>(nodal + (pos0 + r) * 256 + seg * 128);
        half2* drow = reinterpret_cast<half2*>(Xs + r * XP + seg * 128);
#pragma unroll
        for (int i = 0; i < 32; i++) {
            float4 v = src[i];
            drow[i * 2]     = __floats2half2_rn(v.x, v.y);
            drow[i * 2 + 1] = __floats2half2_rn(v.z, v.w);
        }
    }

    for (int c = 0; c < 24; c++) {
        float acc[4][4][4];
#pragma unroll
        for (int mt = 0; mt < 4; mt++)
#pragma unroll
            for (int nt = 0; nt < 4; nt++)
#pragma unroll
                for (int q = 0; q < 4; q++) acc[mt][nt][q] = 0.f;

#pragma unroll
        for (int kc = 0; kc < 2; kc++) {
            __syncthreads();   // W/stage buffer free
            {   // load W: 128 rows x 128 k -> 64 halves = 8 uint4 per thread
                const uint4* s4 = reinterpret_cast<const uint4*>(
                    g_WT + ((size_t)c * 128 + r) * 256 + kc * 128 + seg * 64);
                uint4* d4 = reinterpret_cast<uint4*>(Ws + r * WP + seg * 64);
#pragma unroll
                for (int i = 0; i < 8; i++) d4[i] = s4[i];
            }
            __syncthreads();

#pragma unroll
            for (int k0 = 0; k0 < 128; k0 += 32) {
                uint32_t b[4][4];
#pragma unroll
                for (int nt = 0; nt < 4; nt++) {
                    const uint32_t bd = sb + K1_WOFF +
                        (((wn * 32 + nt * 8 + (lane & 7)) * WP + k0 + ((lane >> 3) << 3)) << 1);
                    LDM_X4(b[nt][0], b[nt][1], b[nt][2], b[nt][3], bd);
                }
#pragma unroll
                for (int half = 0; half < 2; half++) {
                    uint32_t a[4][4];
#pragma unroll
                    for (int mt = 0; mt < 4; mt++) {
                        const uint32_t ad = sb +
                            (((wm * 64 + mt * 16 + (lane & 15)) * XP
                              + kc * 128 + k0 + half * 16 + ((lane >> 4) << 3)) << 1);
                        LDM_X4(a[mt][0], a[mt][1], a[mt][2], a[mt][3], ad);
                    }
#pragma unroll
                    for (int mt = 0; mt < 4; mt++)
#pragma unroll
                        for (int nt = 0; nt < 4; nt++)
                            MMA16816(acc[mt][nt], a[mt][0], a[mt][1], a[mt][2], a[mt][3],
                                     b[nt][half * 2], b[nt][half * 2 + 1]);
                }
            }
        }
        __syncthreads();   // all W reads done; buffer becomes staging

        // stage accumulators as fp16 (pitch 68 half2 = 136 halves)
        {
            half2* stg = (half2*)Ws;
            const int g = lane >> 2, t4 = lane & 3;
#pragma unroll
            for (int mt = 0; mt < 4; mt++)
#pragma unroll
                for (int nt = 0; nt < 4; nt++) {
                    const int row = wm * 64 + mt * 16 + g;
                    const int col = wn * 32 + nt * 8 + t4 * 2;
                    stg[row * 68 + (col >> 1)]       = __floats2half2_rn(acc[mt][nt][0], acc[mt][nt][1]);
                    stg[(row + 8) * 68 + (col >> 1)] = __floats2half2_rn(acc[mt][nt][2], acc[mt][nt][3]);
                }
        }
        __syncthreads();

        // coalesced writeback: 64 halves = 8 uint4 per thread
        {
            const uint4* s4 = reinterpret_cast<const uint4*>(Ws + r * 136 + seg * 64);
            uint4* d4 = reinterpret_cast<uint4*>(g_Ch + (pos0 + r) * 3072 + c * 128 + seg * 64);
#pragma unroll
            for (int i = 0; i < 8; i++) d4[i] = s4[i];
        }
    }
}

// ============================ K2: pointwise ============================
__device__ __forceinline__ void load64(float* dst, const __half* src)
{
    const uint4* s4 = reinterpret_cast<const uint4*>(src);
#pragma unroll
    for (int u = 0; u < 8; u++) {
        uint4 v = s4[u];
        float2 f0 = __half22float2(*reinterpret_cast<half2*>(&v.x));
        float2 f1 = __half22float2(*reinterpret_cast<half2*>(&v.y));
        float2 f2 = __half22float2(*reinterpret_cast<half2*>(&v.z));
        float2 f3 = __half22float2(*reinterpret_cast<half2*>(&v.w));
        dst[u * 8 + 0] = f0.x; dst[u * 8 + 1] = f0.y;
        dst[u * 8 + 2] = f1.x; dst[u * 8 + 3] = f1.y;
        dst[u * 8 + 4] = f2.x; dst[u * 8 + 5] = f2.y;
        dst[u * 8 + 6] = f3.x; dst[u * 8 + 7] = f3.y;
    }
}

__device__ __forceinline__ void lnrot_t(float* x, const float* __restrict__ bias,
                                        const float* __restrict__ g,
                                        const float* __restrict__ b,
                                        const float* __restrict__ ct,
                                        const float* __restrict__ st, int p)
{
    float mu = 0.f;
#pragma unroll
    for (int j = 0; j < 64; j++) { x[j] += bias[j]; mu += x[j]; }
    mu *= (1.f / 64.f);
    float var = 0.f;
#pragma unroll
    for (int j = 0; j < 64; j++) { const float d = x[j] - mu; var += d * d; }
    const float rs = rsqrtf(var * (1.f / 64.f) + EPS_);
#pragma unroll
    for (int j = 0; j < 64; j++) x[j] = (x[j] - mu) * rs * g[j] + b[j];
#pragma unroll
    for (int j = 0; j < 32; j++) {
        const float c = ct[j * 32 + p], s = st[j * 32 + p];
        const float f = x[j], gg = x[j + 32];
        x[j]      = c + (c * f - s * gg);
        x[j + 32] = s + (s * f + c * gg);
    }
}

__global__ void __launch_bounds__(256)
k2_attn(const float* __restrict__ coords,
        const float* __restrict__ biasQ, const float* __restrict__ biasK,
        const float* __restrict__ lnQg, const float* __restrict__ lnQb,
        const float* __restrict__ lnKg, const float* __restrict__ lnKb)
{
    extern __shared__ __align__(16) float sf[];
    float* buf0 = sf;                      // [512][33]
    float* ctab = sf + 512 * 33;           // [2][32 j][32 p]
    float* stab = ctab + 2048;
    const int tid = threadIdx.x, h = tid >> 5, p = tid & 31;
    const size_t pos0 = (size_t)blockIdx.x * 32;
    const size_t gpos = pos0 + p;
    const __half* Cb = g_Ch + gpos * 3072;

    for (int idx = tid; idx < 2048; idx += 256) {
        const int n = idx >> 10, j = (idx >> 5) & 31, pp = idx & 31;
        const float cd = coords[(pos0 + pp) * 2 + n];
        float s, c;
        sincosf(cd * (float)j, &s, &c);
        ctab[idx] = c;
        stab[idx] = s;
    }
    __syncthreads();

    float acc[8];
#pragma unroll
    for (int i = 0; i < 8; i++) acc[i] = 0.f;

#pragma unroll
    for (int n = 0; n < 2; n++) {
        const float* ct = ctab + n * 1024;
        const float* st = stab + n * 1024;
        float kx[64];
        load64(kx, Cb + 1024 + n * 512 + h * 64);
        lnrot_t(kx, biasK + (n * 8 + h) * 64, lnKg + n * 64, lnKb + n * 64, ct, st, p);
        __syncthreads();
#pragma unroll
        for (int j = 0; j < 64; j++) buf0[(h * 64 + j) * 33 + p] = kx[j];
        float qe[64];
        load64(qe, Cb + n * 512 + h * 64);
        lnrot_t(qe, biasQ + (n * 8 + h) * 64, lnQg + n * 64, lnQb + n * 64, ct, st, p);
        __syncthreads();
#pragma unroll
        for (int h2 = 0; h2 < 8; h2++) {
            float a = 0.f;
#pragma unroll
            for (int j = 0; j < 64; j++) a += qe[j] * buf0[(h2 * 64 + j) * 33 + p];
            acc[h2] += a;
        }
    }
    float pr[8], mx = -1e30f, sum = 0.f;
#pragma unroll
    for (int i = 0; i < 8; i++) { acc[i] *= SCALE_; mx = fmaxf(mx, acc[i]); }
#pragma unroll
    for (int i = 0; i < 8; i++) { pr[i] = expf(acc[i] - mx); sum += pr[i]; }
    const float inv = 1.f / sum;
#pragma unroll
    for (int i = 0; i < 8; i++) pr[i] *= inv;

#pragma unroll
    for (int n = 0; n < 2; n++) {
        float vx[64];
        load64(vx, Cb + 2048 + n * 512 + h * 64);
        __syncthreads();
#pragma unroll
        for (int j = 0; j < 64; j++) buf0[(h * 64 + j) * 33 + p] = vx[j];
        __syncthreads();
        float av[64];
#pragma unroll
        for (int j = 0; j < 64; j++) {
            float a = 0.f;
#pragma unroll
            for (int h2 = 0; h2 < 8; h2++) a += pr[h2] * buf0[(h2 * 64 + j) * 33 + p];
            av[j] = a;
        }
        uint4* d4 = reinterpret_cast<uint4*>(g_A2 + gpos * 1024 + h * 128 + n * 64);
#pragma unroll
        for (int u = 0; u < 8; u++) {
            uint4 v;
            half2 h0 = __floats2half2_rn(av[u * 8 + 0], av[u * 8 + 1]);
            half2 h1 = __floats2half2_rn(av[u * 8 + 2], av[u * 8 + 3]);
            half2 h2v = __floats2half2_rn(av[u * 8 + 4], av[u * 8 + 5]);
            half2 h3 = __floats2half2_rn(av[u * 8 + 6], av[u * 8 + 7]);
            v.x = *reinterpret_cast<uint32_t*>(&h0);
            v.y = *reinterpret_cast<uint32_t*>(&h1);
            v.z = *reinterpret_cast<uint32_t*>(&h2v);
            v.w = *reinterpret_cast<uint32_t*>(&h3);
            d4[u] = v;
        }
    }
}

// ============================ K3: output GEMM ============================
// out[pos][c] = A2[pos][1024] * WoT[c][1024]^T + bout.
// CTA = 128 pos x 128 c; warp 64x32 (mt=4, nt=4); smem 69632 -> occ 2.
#define K3_BOFF 34816
#define K3_SMEM 69632

__global__ void __launch_bounds__(256, 2)
k3_out(const float* __restrict__ bout, float* __restrict__ out)
{
    extern __shared__ __align__(16) char sm[];
    __half* As = (__half*)sm;
    __half* Bs = (__half*)(sm + K3_BOFF);
    float*  stage = (float*)sm;              // [128][132] fp32, reuses A+B
    const uint32_t sb = smem_u32(sm);

    const int tid = threadIdx.x, wid = tid >> 5, lane = tid & 31;
    const int wm = wid >> 2, wn = wid & 3;   // warp: rows wm*64, cols wn*32
    const int r = tid >> 1, seg = tid & 1;
    const size_t pos0 = (size_t)(blockIdx.x >> 1) * 128;
    const int c0 = (blockIdx.x & 1) * 128;

    float acc[4][4][4];
#pragma unroll
    for (int mt = 0; mt < 4; mt++)
#pragma unroll
        for (int nt = 0; nt < 4; nt++)
#pragma unroll
            for (int q = 0; q < 4; q++) acc[mt][nt][q] = 0.f;

    for (int kc = 0; kc < 8; kc++) {
        __syncthreads();
        {   // A chunk: 128 rows x 128 k -> 8 uint4 per thread
            const uint4* s4 = reinterpret_cast<const uint4*>(
                g_A2 + (pos0 + r) * 1024 + kc * 128 + seg * 64);
            uint4* d4 = reinterpret_cast<uint4*>(As + r * WP + seg * 64);
#pragma unroll
            for (int i = 0; i < 8; i++) d4[i] = s4[i];
        }
        {   // B chunk: 128 rows x 128 k -> 8 uint4 per thread
            const uint4* s4 = reinterpret_cast<const uint4*>(
                g_WoT + (size_t)(c0 + r) * 1024 + kc * 128 + seg * 64);
            uint4* d4 = reinterpret_cast<uint4*>(Bs + r * WP + seg * 64);
#pragma unroll
            for (int i = 0; i < 8; i++) d4[i] = s4[i];
        }
        __syncthreads();

#pragma unroll
        for (int k0 = 0; k0 < 128; k0 += 32) {
            uint32_t b[4][4];
#pragma unroll
            for (int nt = 0; nt < 4; nt++) {
                const uint32_t bd = sb + K3_BOFF +
                    (((wn * 32 + nt * 8 + (lane & 7)) * WP + k0 + ((lane >> 3) << 3)) << 1);
                LDM_X4(b[nt][0], b[nt][1], b[nt][2], b[nt][3], bd);
            }
#pragma unroll
            for (int half = 0; half < 2; half++) {
                uint32_t a[4][4];
#pragma unroll
                for (int mt = 0; mt < 4; mt++) {
                    const uint32_t ad = sb +
                        (((wm * 64 + mt * 16 + (lane & 15)) * WP
                          + k0 + half * 16 + ((lane >> 4) << 3)) << 1);
                    LDM_X4(a[mt][0], a[mt][1], a[mt][2], a[mt][3], ad);
                }
#pragma unroll
                for (int mt = 0; mt < 4; mt++)
#pragma unroll
                    for (int nt = 0; nt < 4; nt++)
                        MMA16816(acc[mt][nt], a[mt][0], a[mt][1], a[mt][2], a[mt][3],
                                 b[nt][half * 2], b[nt][half * 2 + 1]);
            }
        }
    }
    __syncthreads();
    // stage fp32 result (pitch 132 floats)
    {
        const int g = lane >> 2, t4 = lane & 3;
#pragma unroll
        for (int mt = 0; mt < 4; mt++)
#pragma unroll
            for (int nt = 0; nt < 4; nt++) {
                const int row = wm * 64 + mt * 16 + g;
                const int col = wn * 32 + nt * 8 + t4 * 2;
                stage[row * 132 + col]           = acc[mt][nt][0];
                stage[row * 132 + col + 1]       = acc[mt][nt][1];
                stage[(row + 8) * 132 + col]     = acc[mt][nt][2];
                stage[(row + 8) * 132 + col + 1] = acc[mt][nt][3];
            }
    }
    __syncthreads();
    {
        float* drow = out + (pos0 + r) * 256 + c0 + seg * 64;
        const float* srow = stage + r * 132 + seg * 64;
        const float* brow = bout + c0 + seg * 64;
#pragma unroll
        for (int i = 0; i < 16; i++) {
            float4 v = *reinterpret_cast<const float4*>(srow + i * 4);
            float4 bb = *reinterpret_cast<const float4*>(brow + i * 4);
            v.x += bb.x; v.y += bb.y; v.z += bb.z; v.w += bb.w;
            *reinterpret_cast<float4*>(drow + i * 4) = v;
        }
    }
}

// ---------------------------------------------------------------------------
extern "C" void kernel_launch(void* const* d_in, const int* in_sizes, int n_in,
                              void* d_out, int out_size)
{
    const float* nodal  = (const float*)d_in[0];
    const float* coords = (const float*)d_in[1];
    const float* WQ     = (const float*)d_in[2];
    const float* WK     = (const float*)d_in[3];
    const float* WV     = (const float*)d_in[4];
    const float* biasQ  = (const float*)d_in[5];
    const float* biasK  = (const float*)d_in[6];
    const float* lnQg   = (const float*)d_in[7];
    const float* lnQb   = (const float*)d_in[8];
    const float* lnKg   = (const float*)d_in[9];
    const float* lnKb   = (const float*)d_in[10];
    const float* Wout   = (const float*)d_in[11];
    const float* bout   = (const float*)d_in[12];
    float* out = (float*)d_out;

    cudaFuncSetAttribute(k1_proj, cudaFuncAttributeMaxDynamicSharedMemorySize, K1_SMEM);
    cudaFuncSetAttribute(k2_attn, cudaFuncAttributeMaxDynamicSharedMemorySize, 83968);
    cudaFuncSetAttribute(k3_out,  cudaFuncAttributeMaxDynamicSharedMemorySize, K3_SMEM);

    k0_prep<<<4096, 256>>>(WQ, WK, WV, Wout);
    k1_proj<<<512, 256, K1_SMEM>>>(nodal);
    k2_attn<<<2048, 256, 83968>>>(coords, biasQ, biasK, lnQg, lnQb, lnKg, lnKb);
    k3_out<<<1024, 256, K3_SMEM>>>(bout, out);
}